// round 1
// baseline (speedup 1.0000x reference)
#include <cuda_runtime.h>
#include <cuda_bf16.h>
#include <math.h>

// Problem constants (fixed by dataset)
#define NN      100000          // nodes
#define EMAX    1600000         // edges before self loops
#define ETOT    (EMAX + NN)     // with self loops
#define FIN     128
#define DD      64              // H*C
#define HH      8
#define GG      64
#define NCLS    10
#define SLOPE   0.2f

// ---------------- scratch (static device globals; no allocation) -------------
__device__ float g_hA[NN * DD];      // layer output / next layer input
__device__ float g_hP[NN * DD];      // projected features (pre-attention)
__device__ float g_als[NN * HH];     // alpha_src logits
__device__ float g_ald[NN * HH];     // alpha_dst logits
__device__ int   g_counts[NN];
__device__ int   g_row_ptr[NN + 1];
__device__ int   g_cursor[NN];
__device__ int   g_csr_src[ETOT];
__device__ float g_sums[GG * DD];
__device__ float g_cnt[GG];

// ---------------- CSR build --------------------------------------------------
__global__ void init_counts_kernel() {
    int i = blockIdx.x * blockDim.x + threadIdx.x;
    if (i < NN) g_counts[i] = 1;   // self loop
}

__global__ void hist_kernel(const int* __restrict__ dst, int e) {
    int i = blockIdx.x * blockDim.x + threadIdx.x;
    if (i < e) atomicAdd(&g_counts[dst[i]], 1);
}

// single-block exclusive scan of g_counts -> g_row_ptr / g_cursor
__global__ void scan_kernel() {
    __shared__ int warpsums[32];
    __shared__ int s_carry;
    __shared__ int s_total;
    int tid = threadIdx.x, lane = tid & 31, wid = tid >> 5;
    if (tid == 0) s_carry = 0;
    __syncthreads();
    for (int base = 0; base < NN; base += 1024) {
        int i = base + tid;
        int v = (i < NN) ? g_counts[i] : 0;
        int incl = v;
        #pragma unroll
        for (int off = 1; off < 32; off <<= 1) {
            int t = __shfl_up_sync(0xffffffffu, incl, off);
            if (lane >= off) incl += t;
        }
        if (lane == 31) warpsums[wid] = incl;
        __syncthreads();
        if (wid == 0) {
            int w = warpsums[lane];
            int wi = w;
            #pragma unroll
            for (int off = 1; off < 32; off <<= 1) {
                int t = __shfl_up_sync(0xffffffffu, wi, off);
                if (lane >= off) wi += t;
            }
            warpsums[lane] = wi - w;          // exclusive warp offset
            if (lane == 31) s_total = wi;     // chunk total
        }
        __syncthreads();
        int excl = s_carry + warpsums[wid] + (incl - v);
        if (i < NN) { g_row_ptr[i] = excl; g_cursor[i] = excl; }
        __syncthreads();
        if (tid == 0) s_carry += s_total;
        __syncthreads();
    }
    if (threadIdx.x == 0) g_row_ptr[NN] = s_carry;
}

__global__ void scatter_kernel(const int* __restrict__ src,
                               const int* __restrict__ dst, int e) {
    int i = blockIdx.x * blockDim.x + threadIdx.x;
    int tot = e + NN;
    if (i >= tot) return;
    if (i < e) {
        int d = dst[i];
        int pos = atomicAdd(&g_cursor[d], 1);
        g_csr_src[pos] = src[i];
    } else {
        int n = i - e;                  // self loop
        int pos = atomicAdd(&g_cursor[n], 1);
        g_csr_src[pos] = n;
    }
}

// ---------------- projection GEMM + attention logits -------------------------
// block: 128 threads = 16 nodes x 8 heads; each thread computes 8 channels of
// one head for one node, then the per-head a_src/a_dst dot in the epilogue.
template <int F>
__global__ void gemm_att_kernel(const float* __restrict__ in,
                                const float* __restrict__ W,
                                const float* __restrict__ a_src,
                                const float* __restrict__ a_dst) {
    __shared__ float sW[F * DD];
    __shared__ float sIn[16][F];
    __shared__ float sAs[DD], sAd[DD];
    int tid = threadIdx.x;
    for (int i = tid; i < F * DD; i += 128) sW[i] = W[i];
    if (tid < DD) { sAs[tid] = a_src[tid]; sAd[tid] = a_dst[tid]; }
    int nodeBase = blockIdx.x * 16;
    for (int i = tid; i < 16 * F; i += 128) {
        int nl = i / F, k = i % F;
        int n = nodeBase + nl;
        sIn[nl][k] = (n < NN) ? in[n * F + k] : 0.f;
    }
    __syncthreads();

    int nl = tid >> 3;
    int head = tid & 7;
    int dbase = head * 8;
    float acc[8] = {0, 0, 0, 0, 0, 0, 0, 0};
    #pragma unroll 8
    for (int k = 0; k < F; k++) {
        float xv = sIn[nl][k];
        const float4* w4 = reinterpret_cast<const float4*>(&sW[k * DD + dbase]);
        float4 wa = w4[0], wb = w4[1];
        acc[0] += xv * wa.x; acc[1] += xv * wa.y;
        acc[2] += xv * wa.z; acc[3] += xv * wa.w;
        acc[4] += xv * wb.x; acc[5] += xv * wb.y;
        acc[6] += xv * wb.z; acc[7] += xv * wb.w;
    }

    float as_ = 0.f, ad_ = 0.f;
    #pragma unroll
    for (int j = 0; j < 8; j++) {
        as_ += acc[j] * sAs[dbase + j];
        ad_ += acc[j] * sAd[dbase + j];
    }
    int n = nodeBase + nl;
    if (n < NN) {
        float4* o4 = reinterpret_cast<float4*>(&g_hP[n * DD + dbase]);
        o4[0] = make_float4(acc[0], acc[1], acc[2], acc[3]);
        o4[1] = make_float4(acc[4], acc[5], acc[6], acc[7]);
        g_als[n * HH + head] = as_;
        g_ald[n * HH + head] = ad_;
    }
}

// ---------------- attention aggregation (one warp per dst node) --------------
// pass 1: per-head max over incoming edges ((edge,head)-pair parallel)
// pass 2: sequential edges, 64-wide weighted accumulation in registers
__global__ void attn_kernel(const float* __restrict__ bias,
                            float* __restrict__ hout) {
    int gwarp = (blockIdx.x * blockDim.x + threadIdx.x) >> 5;
    int lane = threadIdx.x & 31;
    if (gwarp >= NN) return;
    int n = gwarp;
    int rs = g_row_ptr[n];
    int re = g_row_ptr[n + 1];
    int myhead = lane & 7;
    float ad = g_ald[n * HH + myhead];

    // pass 1: max
    float mx = -1e30f;
    int npairs = (re - rs) * 8;
    for (int p = lane; p < npairs; p += 32) {
        int s = g_csr_src[rs + (p >> 3)];
        float v = g_als[s * HH + myhead] + ad;
        v = v > 0.f ? v : SLOPE * v;
        mx = fmaxf(mx, v);
    }
    mx = fmaxf(mx, __shfl_xor_sync(0xffffffffu, mx, 8));
    mx = fmaxf(mx, __shfl_xor_sync(0xffffffffu, mx, 16));
    // lanes 0-7 now hold max for heads 0-7 (replicated every 8 lanes)

    int h0 = lane >> 3;       // head of channel d = lane
    int h1 = h0 + 4;          // head of channel d = lane + 32
    float acc0 = 0.f, acc1 = 0.f, sumex = 0.f;
    float mym = mx;           // lanes 0-7: max of own head

    for (int i = rs; i < re; i++) {
        int s = g_csr_src[i];
        float p8 = 0.f;
        if (lane < 8) {
            float v = g_als[s * HH + lane] + ad;
            v = v > 0.f ? v : SLOPE * v;
            p8 = __expf(v - mym);
            sumex += p8;
        }
        float p0 = __shfl_sync(0xffffffffu, p8, h0);
        float p1 = __shfl_sync(0xffffffffu, p8, h1);
        acc0 += g_hP[s * DD + lane] * p0;
        acc1 += g_hP[s * DD + 32 + lane] * p1;
    }
    float d0 = __shfl_sync(0xffffffffu, sumex, h0);
    float d1 = __shfl_sync(0xffffffffu, sumex, h1);
    float o0 = acc0 / d0 + bias[lane];
    float o1 = acc1 / d1 + bias[32 + lane];
    o0 = o0 > 0.f ? o0 : expm1f(o0);   // ELU
    o1 = o1 > 0.f ? o1 : expm1f(o1);
    hout[n * DD + lane] = o0;
    hout[n * DD + 32 + lane] = o1;
}

// ---------------- pooling + head ---------------------------------------------
__global__ void zero_pool_kernel() {
    int i = threadIdx.x;
    for (int k = i; k < GG * DD; k += blockDim.x) g_sums[k] = 0.f;
    if (i < GG) g_cnt[i] = 0.f;
}

// block: 64 threads (one per channel), 64 consecutive nodes; batch is sorted so
// we accumulate per-segment in registers and flush at graph boundaries.
__global__ void pool_kernel(const float* __restrict__ h,
                            const int* __restrict__ batch) {
    const int NPB = 64;
    int d = threadIdx.x;
    int n0 = blockIdx.x * NPB;
    int n1 = min(n0 + NPB, NN);
    if (n0 >= NN) return;
    float local = 0.f, lc = 0.f;
    int cur = batch[n0];
    for (int n = n0; n < n1; n++) {
        int g = batch[n];
        if (g != cur) {
            atomicAdd(&g_sums[cur * DD + d], local);
            if (d == 0) atomicAdd(&g_cnt[cur], lc);
            local = 0.f; lc = 0.f; cur = g;
        }
        local += h[n * DD + d];
        lc += 1.f;
    }
    atomicAdd(&g_sums[cur * DD + d], local);
    if (d == 0) atomicAdd(&g_cnt[cur], lc);
}

__global__ void final_kernel(const float* __restrict__ lw,
                             const float* __restrict__ lb,
                             float* __restrict__ out) {
    int t = threadIdx.x;
    if (t >= GG * NCLS) return;
    int g = t / NCLS, c = t % NCLS;
    float cnt = fmaxf(g_cnt[g], 1.f);
    float acc = lb[c];
    for (int d = 0; d < DD; d++)
        acc += (g_sums[g * DD + d] / cnt) * lw[d * NCLS + c];
    out[t] = acc;
}

// ---------------- launch ------------------------------------------------------
extern "C" void kernel_launch(void* const* d_in, const int* in_sizes, int n_in,
                              void* d_out, int out_size) {
    const float* x    = (const float*)d_in[0];
    const int*   ei   = (const int*)d_in[1];
    const int*   batch= (const int*)d_in[2];
    const float* W1   = (const float*)d_in[3];
    const float* a1s  = (const float*)d_in[4];
    const float* a1d  = (const float*)d_in[5];
    const float* b1   = (const float*)d_in[6];
    const float* W2   = (const float*)d_in[7];
    const float* a2s  = (const float*)d_in[8];
    const float* a2d  = (const float*)d_in[9];
    const float* b2   = (const float*)d_in[10];
    const float* W3   = (const float*)d_in[11];
    const float* a3s  = (const float*)d_in[12];
    const float* a3d  = (const float*)d_in[13];
    const float* b3   = (const float*)d_in[14];
    const float* linW = (const float*)d_in[15];
    const float* linb = (const float*)d_in[16];
    float* out = (float*)d_out;

    int E = in_sizes[1] / 2;           // edges (2,E)
    const int* src = ei;
    const int* dst = ei + E;

    // CSR build (once; shared by all 3 layers)
    init_counts_kernel<<<(NN + 255) / 256, 256>>>();
    hist_kernel<<<(E + 255) / 256, 256>>>(dst, E);
    scan_kernel<<<1, 1024>>>();
    scatter_kernel<<<(E + NN + 255) / 256, 256>>>(src, dst, E);

    // layer 1
    gemm_att_kernel<FIN><<<(NN + 15) / 16, 128>>>(x, W1, a1s, a1d);
    attn_kernel<<<(NN * 32 + 255) / 256, 256>>>(b1, g_hA);
    // layer 2
    gemm_att_kernel<DD><<<(NN + 15) / 16, 128>>>(g_hA, W2, a2s, a2d);
    attn_kernel<<<(NN * 32 + 255) / 256, 256>>>(b2, g_hA);
    // layer 3
    gemm_att_kernel<DD><<<(NN + 15) / 16, 128>>>(g_hA, W3, a3s, a3d);
    attn_kernel<<<(NN * 32 + 255) / 256, 256>>>(b3, g_hA);

    // pool + classifier
    zero_pool_kernel<<<1, 256>>>();
    pool_kernel<<<(NN + 63) / 64, 64>>>(g_hA, batch);
    final_kernel<<<1, GG * NCLS>>>(linW, linb, out);
}

// round 3
// speedup vs baseline: 1.3103x; 1.3103x over previous
#include <cuda_runtime.h>
#include <cuda_bf16.h>
#include <math.h>

// Problem constants (fixed by dataset)
#define NN      100000          // nodes
#define EMAX    1600000         // edges before self loops
#define ETOT    (EMAX + NN)     // with self loops
#define FIN     128
#define DD      64              // H*C
#define HH      8
#define GG      64
#define NCLS    10
#define SLOPE   0.2f

// ---------------- scratch (static device globals; no allocation) -------------
__device__ float g_hA[NN * DD];      // layer output / next layer input
__device__ float g_hP[NN * DD];      // projected features (pre-attention)
__device__ float g_als[NN * HH];     // alpha_src logits
__device__ float g_ald[NN * HH];     // alpha_dst logits
__device__ int   g_counts[NN];
__device__ int   g_row_ptr[NN + 1];
__device__ int   g_cursor[NN];
__device__ int   g_csr_src[ETOT];
__device__ float g_sums[GG * DD];
__device__ float g_cnt[GG];

// ---------------- CSR build --------------------------------------------------
__global__ void init_counts_kernel() {
    int i = blockIdx.x * blockDim.x + threadIdx.x;
    if (i < NN) g_counts[i] = 1;   // self loop
}

__global__ void hist_kernel(const int* __restrict__ dst, int e) {
    int i = blockIdx.x * blockDim.x + threadIdx.x;
    if (i < e) atomicAdd(&g_counts[dst[i]], 1);
}

// single-block exclusive scan of g_counts -> g_row_ptr / g_cursor
__global__ void scan_kernel() {
    __shared__ int warpsums[32];
    __shared__ int s_carry;
    __shared__ int s_total;
    int tid = threadIdx.x, lane = tid & 31, wid = tid >> 5;
    if (tid == 0) s_carry = 0;
    __syncthreads();
    for (int base = 0; base < NN; base += 1024) {
        int i = base + tid;
        int v = (i < NN) ? g_counts[i] : 0;
        int incl = v;
        #pragma unroll
        for (int off = 1; off < 32; off <<= 1) {
            int t = __shfl_up_sync(0xffffffffu, incl, off);
            if (lane >= off) incl += t;
        }
        if (lane == 31) warpsums[wid] = incl;
        __syncthreads();
        if (wid == 0) {
            int w = warpsums[lane];
            int wi = w;
            #pragma unroll
            for (int off = 1; off < 32; off <<= 1) {
                int t = __shfl_up_sync(0xffffffffu, wi, off);
                if (lane >= off) wi += t;
            }
            warpsums[lane] = wi - w;          // exclusive warp offset
            if (lane == 31) s_total = wi;     // chunk total
        }
        __syncthreads();
        int excl = s_carry + warpsums[wid] + (incl - v);
        if (i < NN) { g_row_ptr[i] = excl; g_cursor[i] = excl; }
        __syncthreads();
        if (tid == 0) s_carry += s_total;
        __syncthreads();
    }
    if (threadIdx.x == 0) g_row_ptr[NN] = s_carry;
}

__global__ void scatter_kernel(const int* __restrict__ src,
                               const int* __restrict__ dst, int e) {
    int i = blockIdx.x * blockDim.x + threadIdx.x;
    int tot = e + NN;
    if (i >= tot) return;
    if (i < e) {
        int d = dst[i];
        int pos = atomicAdd(&g_cursor[d], 1);
        g_csr_src[pos] = src[i];
    } else {
        int n = i - e;                  // self loop
        int pos = atomicAdd(&g_cursor[n], 1);
        g_csr_src[pos] = n;
    }
}

// ---------------- projection GEMM + attention logits -------------------------
// block: 128 threads = 16 node-groups x 8 heads; each thread computes 8
// channels of one head for FOUR nodes (32 accumulators). K staged in chunks
// of 64 so smem stays under 48KB for F=128.
template <int F>
__global__ void gemm_att_kernel(const float* __restrict__ in,
                                const float* __restrict__ W,
                                const float* __restrict__ a_src,
                                const float* __restrict__ a_dst) {
    constexpr int KC = 64;
    constexpr int NCH = F / KC;            // 1 or 2 chunks
    __shared__ float sW[KC * DD];          // 16KB
    __shared__ float sIn[64][KC + 1];      // 16.25KB (padded vs bank conflicts)

    int tid = threadIdx.x;
    int head = tid & 7;
    int ng = tid >> 3;                     // 0..15
    int dbase = head * 8;
    int nodeBase = blockIdx.x * 64;

    float acc[4][8];
    #pragma unroll
    for (int i = 0; i < 4; i++)
        #pragma unroll
        for (int j = 0; j < 8; j++) acc[i][j] = 0.f;

    for (int kc = 0; kc < NCH; kc++) {
        // stage W chunk: contiguous KC*DD floats
        const float4* W4 = reinterpret_cast<const float4*>(W + kc * KC * DD);
        float4* sW4 = reinterpret_cast<float4*>(sW);
        #pragma unroll
        for (int r = 0; r < (KC * DD / 4) / 128; r++)
            sW4[tid + 128 * r] = W4[tid + 128 * r];
        // stage input tile: 64 nodes x KC floats
        #pragma unroll
        for (int r = 0; r < (64 * KC / 4) / 128; r++) {
            int idx = tid + 128 * r;
            int nl = idx >> 4;             // node-local (KC/4 = 16 vec4 per node)
            int k4 = idx & 15;
            int n = nodeBase + nl;
            float4 v = make_float4(0.f, 0.f, 0.f, 0.f);
            if (n < NN)
                v = *reinterpret_cast<const float4*>(in + n * F + kc * KC + k4 * 4);
            sIn[nl][k4 * 4 + 0] = v.x;
            sIn[nl][k4 * 4 + 1] = v.y;
            sIn[nl][k4 * 4 + 2] = v.z;
            sIn[nl][k4 * 4 + 3] = v.w;
        }
        __syncthreads();

        #pragma unroll 8
        for (int k = 0; k < KC; k++) {
            const float4* w4 = reinterpret_cast<const float4*>(&sW[k * DD + dbase]);
            float4 wa = w4[0], wb = w4[1];
            #pragma unroll
            for (int i = 0; i < 4; i++) {
                float xv = sIn[ng * 4 + i][k];
                acc[i][0] += xv * wa.x; acc[i][1] += xv * wa.y;
                acc[i][2] += xv * wa.z; acc[i][3] += xv * wa.w;
                acc[i][4] += xv * wb.x; acc[i][5] += xv * wb.y;
                acc[i][6] += xv * wb.z; acc[i][7] += xv * wb.w;
            }
        }
        __syncthreads();
    }

    // epilogue: attention logits + store
    float4 as4a = *reinterpret_cast<const float4*>(a_src + dbase);
    float4 as4b = *reinterpret_cast<const float4*>(a_src + dbase + 4);
    float4 ad4a = *reinterpret_cast<const float4*>(a_dst + dbase);
    float4 ad4b = *reinterpret_cast<const float4*>(a_dst + dbase + 4);
    #pragma unroll
    for (int i = 0; i < 4; i++) {
        int n = nodeBase + ng * 4 + i;
        if (n >= NN) continue;
        float as_ = acc[i][0] * as4a.x + acc[i][1] * as4a.y + acc[i][2] * as4a.z
                  + acc[i][3] * as4a.w + acc[i][4] * as4b.x + acc[i][5] * as4b.y
                  + acc[i][6] * as4b.z + acc[i][7] * as4b.w;
        float ad_ = acc[i][0] * ad4a.x + acc[i][1] * ad4a.y + acc[i][2] * ad4a.z
                  + acc[i][3] * ad4a.w + acc[i][4] * ad4b.x + acc[i][5] * ad4b.y
                  + acc[i][6] * ad4b.z + acc[i][7] * ad4b.w;
        float4* o4 = reinterpret_cast<float4*>(&g_hP[n * DD + dbase]);
        o4[0] = make_float4(acc[i][0], acc[i][1], acc[i][2], acc[i][3]);
        o4[1] = make_float4(acc[i][4], acc[i][5], acc[i][6], acc[i][7]);
        g_als[n * HH + head] = as_;
        g_ald[n * HH + head] = ad_;
    }
}

// ---------------- attention aggregation (one warp per dst node) --------------
// Single pass (softmax is shift-invariant; logits are O(1) so no max needed).
// Per batch of 32 edges: coalesced csr_src load; each lane computes all 8
// heads' exp(leakyrelu(.)) for its edge and stages them in smem; then the
// accumulation loop gathers hP as float2/lane with the staged weights.
__global__ void attn_kernel(const float* __restrict__ bias,
                            float* __restrict__ hout) {
    __shared__ float s_p[8][256];
    int warp = threadIdx.x >> 5;
    int lane = threadIdx.x & 31;
    int n = blockIdx.x * 8 + warp;
    if (n >= NN) return;
    int rs = g_row_ptr[n];
    int re = g_row_ptr[n + 1];

    float4 adA = *reinterpret_cast<const float4*>(&g_ald[n * HH]);
    float4 adB = *reinterpret_cast<const float4*>(&g_ald[n * HH + 4]);

    int h = lane >> 2;                 // head of channels 2*lane, 2*lane+1
    float accx = 0.f, accy = 0.f, sumex = 0.f;
    float* sp = s_p[warp];

    for (int base = rs; base < re; base += 32) {
        int nb = min(32, re - base);
        int s = 0;
        if (lane < nb) s = g_csr_src[base + lane];
        if (lane < nb) {
            float4 lA = *reinterpret_cast<const float4*>(&g_als[s * HH]);
            float4 lB = *reinterpret_cast<const float4*>(&g_als[s * HH + 4]);
            float e0 = lA.x + adA.x, e1 = lA.y + adA.y;
            float e2 = lA.z + adA.z, e3 = lA.w + adA.w;
            float e4 = lB.x + adB.x, e5 = lB.y + adB.y;
            float e6 = lB.z + adB.z, e7 = lB.w + adB.w;
            e0 = e0 > 0.f ? e0 : SLOPE * e0; e1 = e1 > 0.f ? e1 : SLOPE * e1;
            e2 = e2 > 0.f ? e2 : SLOPE * e2; e3 = e3 > 0.f ? e3 : SLOPE * e3;
            e4 = e4 > 0.f ? e4 : SLOPE * e4; e5 = e5 > 0.f ? e5 : SLOPE * e5;
            e6 = e6 > 0.f ? e6 : SLOPE * e6; e7 = e7 > 0.f ? e7 : SLOPE * e7;
            float4* p4 = reinterpret_cast<float4*>(&sp[lane * 8]);
            p4[0] = make_float4(__expf(e0), __expf(e1), __expf(e2), __expf(e3));
            p4[1] = make_float4(__expf(e4), __expf(e5), __expf(e6), __expf(e7));
        }
        __syncwarp();
        #pragma unroll 4
        for (int j = 0; j < nb; j++) {
            int sj = __shfl_sync(0xffffffffu, s, j);
            float p = sp[j * 8 + h];
            float2 f = *reinterpret_cast<const float2*>(&g_hP[sj * DD + 2 * lane]);
            accx += f.x * p;
            accy += f.y * p;
            if (lane < 8) sumex += sp[j * 8 + lane];
        }
        __syncwarp();
    }

    float denom = __shfl_sync(0xffffffffu, sumex, h);
    float o0 = accx / denom + bias[2 * lane];
    float o1 = accy / denom + bias[2 * lane + 1];
    o0 = o0 > 0.f ? o0 : expm1f(o0);   // ELU
    o1 = o1 > 0.f ? o1 : expm1f(o1);
    *reinterpret_cast<float2*>(&hout[n * DD + 2 * lane]) = make_float2(o0, o1);
}

// ---------------- pooling + head ---------------------------------------------
__global__ void zero_pool_kernel() {
    int i = threadIdx.x;
    for (int k = i; k < GG * DD; k += blockDim.x) g_sums[k] = 0.f;
    if (i < GG) g_cnt[i] = 0.f;
}

// block: 64 threads (one per channel), 64 consecutive nodes; batch is sorted so
// we accumulate per-segment in registers and flush at graph boundaries.
__global__ void pool_kernel(const float* __restrict__ h,
                            const int* __restrict__ batch) {
    const int NPB = 64;
    int d = threadIdx.x;
    int n0 = blockIdx.x * NPB;
    int n1 = min(n0 + NPB, NN);
    if (n0 >= NN) return;
    float local = 0.f, lc = 0.f;
    int cur = batch[n0];
    for (int n = n0; n < n1; n++) {
        int g = batch[n];
        if (g != cur) {
            atomicAdd(&g_sums[cur * DD + d], local);
            if (d == 0) atomicAdd(&g_cnt[cur], lc);
            local = 0.f; lc = 0.f; cur = g;
        }
        local += h[n * DD + d];
        lc += 1.f;
    }
    atomicAdd(&g_sums[cur * DD + d], local);
    if (d == 0) atomicAdd(&g_cnt[cur], lc);
}

__global__ void final_kernel(const float* __restrict__ lw,
                             const float* __restrict__ lb,
                             float* __restrict__ out) {
    int t = threadIdx.x;
    if (t >= GG * NCLS) return;
    int g = t / NCLS, c = t % NCLS;
    float cnt = fmaxf(g_cnt[g], 1.f);
    float acc = lb[c];
    for (int d = 0; d < DD; d++)
        acc += (g_sums[g * DD + d] / cnt) * lw[d * NCLS + c];
    out[t] = acc;
}

// ---------------- launch ------------------------------------------------------
extern "C" void kernel_launch(void* const* d_in, const int* in_sizes, int n_in,
                              void* d_out, int out_size) {
    const float* x    = (const float*)d_in[0];
    const int*   ei   = (const int*)d_in[1];
    const int*   batch= (const int*)d_in[2];
    const float* W1   = (const float*)d_in[3];
    const float* a1s  = (const float*)d_in[4];
    const float* a1d  = (const float*)d_in[5];
    const float* b1   = (const float*)d_in[6];
    const float* W2   = (const float*)d_in[7];
    const float* a2s  = (const float*)d_in[8];
    const float* a2d  = (const float*)d_in[9];
    const float* b2   = (const float*)d_in[10];
    const float* W3   = (const float*)d_in[11];
    const float* a3s  = (const float*)d_in[12];
    const float* a3d  = (const float*)d_in[13];
    const float* b3   = (const float*)d_in[14];
    const float* linW = (const float*)d_in[15];
    const float* linb = (const float*)d_in[16];
    float* out = (float*)d_out;

    int E = in_sizes[1] / 2;           // edges (2,E)
    const int* src = ei;
    const int* dst = ei + E;

    // CSR build (once; shared by all 3 layers)
    init_counts_kernel<<<(NN + 255) / 256, 256>>>();
    hist_kernel<<<(E + 255) / 256, 256>>>(dst, E);
    scan_kernel<<<1, 1024>>>();
    scatter_kernel<<<(E + NN + 255) / 256, 256>>>(src, dst, E);

    // layer 1
    gemm_att_kernel<FIN><<<(NN + 63) / 64, 128>>>(x, W1, a1s, a1d);
    attn_kernel<<<(NN + 7) / 8, 256>>>(b1, g_hA);
    // layer 2
    gemm_att_kernel<DD><<<(NN + 63) / 64, 128>>>(g_hA, W2, a2s, a2d);
    attn_kernel<<<(NN + 7) / 8, 256>>>(b2, g_hA);
    // layer 3
    gemm_att_kernel<DD><<<(NN + 63) / 64, 128>>>(g_hA, W3, a3s, a3d);
    attn_kernel<<<(NN + 7) / 8, 256>>>(b3, g_hA);

    // pool + classifier
    zero_pool_kernel<<<1, 256>>>();
    pool_kernel<<<(NN + 63) / 64, 64>>>(g_hA, batch);
    final_kernel<<<1, GG * NCLS>>>(linW, linb, out);
}